// round 2
// baseline (speedup 1.0000x reference)
#include <cuda_runtime.h>
#include <cuda_bf16.h>
#include <math.h>

// Problem constants
#define BS   8
#define NQ   4096          // 64*64
#define E    256
#define NH   8
#define NP   4
#define HD   32            // E/NH
#define HH   64
#define WW   64
#define M_TOT (BS*NQ)      // 32768
#define N1   352           // 256 (value) + 64 (off) + 32 (attn)

// Scratch (device globals; no runtime allocation allowed)
__device__ float g_val [BS*NH*NQ*HD];   // [b,h,pos,d]  8.4M floats
__device__ float g_off [M_TOT*64];      // [m, h*8+p*2+{x,y}]
__device__ float g_attn[M_TOT*32];      // [m, h*4+p]
__device__ float g_samp[M_TOT*E];       // [m, h*32+d]
__device__ float g_w1  [N1*E];          // concat weights
__device__ float g_b1  [N1];            // concat biases

// ---------------------------------------------------------------------------
// Prep: concatenate the three projection weights/biases into one [352,256]
// ---------------------------------------------------------------------------
__global__ void prep_kernel(const float* __restrict__ vw, const float* __restrict__ vb,
                            const float* __restrict__ ow, const float* __restrict__ ob,
                            const float* __restrict__ aw, const float* __restrict__ ab) {
    int i = blockIdx.x * 256 + threadIdx.x;
    if (i < 256*256)      g_w1[i] = vw[i];
    else if (i < 320*256) g_w1[i] = ow[i - 256*256];
    else if (i < 352*256) g_w1[i] = aw[i - 320*256];
    if (i < 256)          g_b1[i] = vb[i];
    else if (i < 320)     g_b1[i] = ob[i - 256];
    else if (i < 352)     g_b1[i] = ab[i - 320];
}

// ---------------------------------------------------------------------------
// GEMM1: query[M,256] @ W1^T[256,352]  (+bias), scatter epilogue
//   c <  256 : value  -> g_val[((b*8+h)*4096+q)*32+d]   (h=c>>5, d=c&31)
//   c <  320 : offsets-> g_off[m*64 + (c-256)]
//   c <  352 : attn   -> g_attn[m*32 + (c-320)]
// Tile: BM=128, BN=64, BK=16; 256 threads, 8x4 micro-tile
// ---------------------------------------------------------------------------
__global__ __launch_bounds__(256) void gemm1_kernel(const float* __restrict__ A) {
    __shared__ float As[16][129];
    __shared__ float Bsh[16][65];
    const int m0 = blockIdx.x * 128;
    const int n0 = blockIdx.y * 64;
    const int tid = threadIdx.x;
    const int tx = tid & 15, ty = tid >> 4;

    float acc[8][4];
    #pragma unroll
    for (int i = 0; i < 8; i++)
        #pragma unroll
        for (int j = 0; j < 4; j++) acc[i][j] = 0.f;

    for (int k0 = 0; k0 < E; k0 += 16) {
        #pragma unroll
        for (int it = 0; it < 8; it++) {
            int idx = tid + it * 256;
            int k = idx & 15, mm = idx >> 4;
            As[k][mm] = A[(m0 + mm) * E + k0 + k];
        }
        #pragma unroll
        for (int it = 0; it < 4; it++) {
            int idx = tid + it * 256;
            int k = idx & 15, nn = idx >> 4;
            int gn = n0 + nn;
            Bsh[k][nn] = (gn < N1) ? g_w1[gn * E + k0 + k] : 0.f;
        }
        __syncthreads();
        #pragma unroll
        for (int k = 0; k < 16; k++) {
            float ra[8], rb[4];
            #pragma unroll
            for (int i = 0; i < 8; i++) ra[i] = As[k][ty + 16 * i];
            #pragma unroll
            for (int j = 0; j < 4; j++) rb[j] = Bsh[k][tx + 16 * j];
            #pragma unroll
            for (int i = 0; i < 8; i++)
                #pragma unroll
                for (int j = 0; j < 4; j++) acc[i][j] = fmaf(ra[i], rb[j], acc[i][j]);
        }
        __syncthreads();
    }

    #pragma unroll
    for (int i = 0; i < 8; i++) {
        int m = m0 + ty + 16 * i;
        int b = m >> 12, q = m & 4095;
        #pragma unroll
        for (int j = 0; j < 4; j++) {
            int c = n0 + tx + 16 * j;
            if (c >= N1) continue;
            float v = acc[i][j] + g_b1[c];
            if (c < 256) {
                int h = c >> 5, d = c & 31;
                g_val[(((b << 3) + h) * NQ + q) * HD + d] = v;
            } else if (c < 320) {
                g_off[m * 64 + (c - 256)] = v;
            } else {
                g_attn[m * 32 + (c - 320)] = v;
            }
        }
    }
}

// ---------------------------------------------------------------------------
// Sampling: one warp per (m, h); lane = channel d.
// softmax over NP=4 attn logits, bilinear zero-padded gather, weighted sum.
// ---------------------------------------------------------------------------
__global__ __launch_bounds__(256) void sample_kernel() {
    const int gid  = blockIdx.x * 8 + (threadIdx.x >> 5);
    const int lane = threadIdx.x & 31;
    const int m = gid >> 3;
    const int h = gid & 7;
    const int b = m >> 12;
    const int q = m & 4095;

    const float* __restrict__ offp = g_off  + m * 64 + h * 8;
    const float* __restrict__ attp = g_attn + m * 32 + h * 4;

    float a0 = attp[0], a1 = attp[1], a2 = attp[2], a3 = attp[3];
    float mx = fmaxf(fmaxf(a0, a1), fmaxf(a2, a3));
    float e0 = __expf(a0 - mx), e1 = __expf(a1 - mx),
          e2 = __expf(a2 - mx), e3 = __expf(a3 - mx);
    float inv = 1.f / (e0 + e1 + e2 + e3);
    float aw[4] = {e0 * inv, e1 * inv, e2 * inv, e3 * inv};

    const float refx = (float)(q & 63) * (1.0f / 63.0f);
    const float refy = (float)(q >> 6) * (1.0f / 63.0f);
    const float* __restrict__ vp = g_val + (size_t)((b << 3) + h) * NQ * HD;

    float acc = 0.f;
    #pragma unroll
    for (int p = 0; p < NP; p++) {
        float px = refx * 64.0f + offp[2 * p]     - 0.5f;
        float py = refy * 64.0f + offp[2 * p + 1] - 0.5f;
        float fx = floorf(px), fy = floorf(py);
        float wx = px - fx, wy = py - fy;
        int x0 = (int)fx, y0 = (int)fy;
        float s = 0.f;
        #pragma unroll
        for (int dy = 0; dy < 2; dy++) {
            #pragma unroll
            for (int dx = 0; dx < 2; dx++) {
                int xi = x0 + dx, yi = y0 + dy;
                if (xi >= 0 && xi < WW && yi >= 0 && yi < HH) {
                    float cw = (dx ? wx : 1.f - wx) * (dy ? wy : 1.f - wy);
                    s = fmaf(cw, vp[(yi * WW + xi) * HD + lane], s);
                }
            }
        }
        acc = fmaf(aw[p], s, acc);
    }
    g_samp[m * E + h * HD + lane] = acc;
}

// ---------------------------------------------------------------------------
// GEMM2: g_samp[M,256] @ out_w^T[256,256] + out_b + 2*query -> out
// ---------------------------------------------------------------------------
__global__ __launch_bounds__(256) void gemm2_kernel(const float* __restrict__ W,
                                                    const float* __restrict__ bias,
                                                    const float* __restrict__ query,
                                                    float* __restrict__ out) {
    __shared__ float As[16][129];
    __shared__ float Bsh[16][65];
    const int m0 = blockIdx.x * 128;
    const int n0 = blockIdx.y * 64;
    const int tid = threadIdx.x;
    const int tx = tid & 15, ty = tid >> 4;

    float acc[8][4];
    #pragma unroll
    for (int i = 0; i < 8; i++)
        #pragma unroll
        for (int j = 0; j < 4; j++) acc[i][j] = 0.f;

    for (int k0 = 0; k0 < E; k0 += 16) {
        #pragma unroll
        for (int it = 0; it < 8; it++) {
            int idx = tid + it * 256;
            int k = idx & 15, mm = idx >> 4;
            As[k][mm] = g_samp[(m0 + mm) * E + k0 + k];
        }
        #pragma unroll
        for (int it = 0; it < 4; it++) {
            int idx = tid + it * 256;
            int k = idx & 15, nn = idx >> 4;
            Bsh[k][nn] = W[(n0 + nn) * E + k0 + k];
        }
        __syncthreads();
        #pragma unroll
        for (int k = 0; k < 16; k++) {
            float ra[8], rb[4];
            #pragma unroll
            for (int i = 0; i < 8; i++) ra[i] = As[k][ty + 16 * i];
            #pragma unroll
            for (int j = 0; j < 4; j++) rb[j] = Bsh[k][tx + 16 * j];
            #pragma unroll
            for (int i = 0; i < 8; i++)
                #pragma unroll
                for (int j = 0; j < 4; j++) acc[i][j] = fmaf(ra[i], rb[j], acc[i][j]);
        }
        __syncthreads();
    }

    #pragma unroll
    for (int i = 0; i < 8; i++) {
        int m = m0 + ty + 16 * i;
        #pragma unroll
        for (int j = 0; j < 4; j++) {
            int c = n0 + tx + 16 * j;
            out[m * E + c] = acc[i][j] + bias[c] + 2.0f * query[m * E + c];
        }
    }
}

// ---------------------------------------------------------------------------
extern "C" void kernel_launch(void* const* d_in, const int* in_sizes, int n_in,
                              void* d_out, int out_size) {
    const float* query   = (const float*)d_in[0];
    const float* value_w = (const float*)d_in[1];
    const float* value_b = (const float*)d_in[2];
    const float* off_w   = (const float*)d_in[3];
    const float* off_b   = (const float*)d_in[4];
    const float* attn_w  = (const float*)d_in[5];
    const float* attn_b  = (const float*)d_in[6];
    const float* out_w   = (const float*)d_in[7];
    const float* out_b   = (const float*)d_in[8];
    float* out = (float*)d_out;

    prep_kernel<<<(N1 * E + 255) / 256, 256>>>(value_w, value_b, off_w, off_b, attn_w, attn_b);

    dim3 g1(M_TOT / 128, (N1 + 63) / 64);
    gemm1_kernel<<<g1, 256>>>(query);

    sample_kernel<<<(M_TOT * NH) / 8, 256>>>();

    dim3 g2(M_TOT / 128, E / 64);
    gemm2_kernel<<<g2, 256>>>(out_w, out_b, query, out);
}

// round 5
// speedup vs baseline: 1.4807x; 1.4807x over previous
#include <cuda_runtime.h>
#include <cuda_bf16.h>
#include <mma.h>
#include <math.h>

using namespace nvcuda;

// Problem constants
#define BS   8
#define NQ   4096          // 64*64
#define E    256
#define NH   8
#define NP   4
#define HD   32            // E/NH
#define HH   64
#define WW   64
#define M_TOT (BS*NQ)      // 32768
#define N1   352           // 256 (value) + 64 (off) + 32 (attn)

// GEMM tiling
#define BM   128
#define BN   64
#define BK   32
#define LDA  36            // BK + 4 pad (multiple of 4 for float4)
#define LDC  72            // BN + 8 pad

// Scratch (device globals; no runtime allocation allowed)
__device__ float g_val [BS*NH*NQ*HD];   // [b,h,pos,d]
__device__ float g_off [M_TOT*64];      // [m, h*8+p*2+{x,y}]
__device__ float g_attn[M_TOT*32];      // [m, h*4+p]
__device__ float g_samp[M_TOT*E];       // [m, h*32+d]
__device__ float g_w1  [N1*E];          // concat weights
__device__ float g_b1  [N1];            // concat biases

// ---------------------------------------------------------------------------
// Prep: concatenate the three projection weights/biases into one [352,256]
// ---------------------------------------------------------------------------
__global__ void prep_kernel(const float* __restrict__ vw, const float* __restrict__ vb,
                            const float* __restrict__ ow, const float* __restrict__ ob,
                            const float* __restrict__ aw, const float* __restrict__ ab) {
    int i = blockIdx.x * 256 + threadIdx.x;
    if (i < 256*256)      g_w1[i] = vw[i];
    else if (i < 320*256) g_w1[i] = ow[i - 256*256];
    else if (i < 352*256) g_w1[i] = aw[i - 320*256];
    if (i < 256)          g_b1[i] = vb[i];
    else if (i < 320)     g_b1[i] = ob[i - 256];
    else if (i < 352)     g_b1[i] = ab[i - 320];
}

// ---------------------------------------------------------------------------
// Shared tf32 mainloop: computes Csh[BM][BN] = A_tile @ B_tile^T in shared.
// A: [M,256] row-major source, B: [N,256] row-major weights (b_rows = rows).
// ---------------------------------------------------------------------------
__device__ __forceinline__ void tf32_mainloop(
    const float* __restrict__ A, const float* __restrict__ Bsrc, int b_rows,
    int m0, int n0, float* smem /* >= BM*LDC floats */)
{
    float* As = smem;                 // [BM][LDA]
    float* Bs = smem + BM * LDA;      // [BN][LDA]
    const int tid = threadIdx.x;
    const int warp = tid >> 5;
    const int wr = warp >> 1;         // 0..3  (row of 32)
    const int wc = warp & 1;          // 0..1  (col of 32)

    wmma::fragment<wmma::accumulator, 16, 16, 8, float> c[2][2];
    #pragma unroll
    for (int i = 0; i < 2; i++)
        #pragma unroll
        for (int j = 0; j < 2; j++) wmma::fill_fragment(c[i][j], 0.0f);

    for (int k0 = 0; k0 < E; k0 += BK) {
        // Load A tile: 128 rows x 8 float4
        #pragma unroll
        for (int it = 0; it < 4; it++) {
            int idx = tid + it * 256;
            int row = idx >> 3, c4 = idx & 7;
            float4 v = *(const float4*)&A[(size_t)(m0 + row) * E + k0 + c4 * 4];
            *(float4*)&As[row * LDA + c4 * 4] = v;
        }
        // Load B tile: 64 rows x 8 float4 (guarded)
        #pragma unroll
        for (int it = 0; it < 2; it++) {
            int idx = tid + it * 256;
            int row = idx >> 3, c4 = idx & 7;
            int gn = n0 + row;
            float4 v = make_float4(0.f, 0.f, 0.f, 0.f);
            if (gn < b_rows) v = *(const float4*)&Bsrc[(size_t)gn * E + k0 + c4 * 4];
            *(float4*)&Bs[row * LDA + c4 * 4] = v;
        }
        __syncthreads();

        #pragma unroll
        for (int kk = 0; kk < BK; kk += 8) {
            wmma::fragment<wmma::matrix_a, 16, 16, 8, wmma::precision::tf32, wmma::row_major> a[2];
            wmma::fragment<wmma::matrix_b, 16, 16, 8, wmma::precision::tf32, wmma::col_major> b[2];
            #pragma unroll
            for (int i = 0; i < 2; i++) {
                wmma::load_matrix_sync(a[i], &As[(wr * 32 + i * 16) * LDA + kk], LDA);
                #pragma unroll
                for (int t = 0; t < a[i].num_elements; t++)
                    a[i].x[t] = wmma::__float_to_tf32(a[i].x[t]);
            }
            #pragma unroll
            for (int j = 0; j < 2; j++) {
                wmma::load_matrix_sync(b[j], &Bs[(wc * 32 + j * 16) * LDA + kk], LDA);
                #pragma unroll
                for (int t = 0; t < b[j].num_elements; t++)
                    b[j].x[t] = wmma::__float_to_tf32(b[j].x[t]);
            }
            #pragma unroll
            for (int i = 0; i < 2; i++)
                #pragma unroll
                for (int j = 0; j < 2; j++)
                    wmma::mma_sync(c[i][j], a[i], b[j], c[i][j]);
        }
        __syncthreads();
    }

    // Stage C into shared (reuses As/Bs region)
    #pragma unroll
    for (int i = 0; i < 2; i++)
        #pragma unroll
        for (int j = 0; j < 2; j++)
            wmma::store_matrix_sync(&smem[(wr * 32 + i * 16) * LDC + wc * 32 + j * 16],
                                    c[i][j], LDC, wmma::mem_row_major);
    __syncthreads();
}

// ---------------------------------------------------------------------------
// GEMM1: query[M,256] @ W1^T[256,352]  (+bias), scatter epilogue
// ---------------------------------------------------------------------------
__global__ __launch_bounds__(256) void gemm1_tc(const float* __restrict__ A) {
    __shared__ float smem[BM * LDC];   // 36 KB; holds As+Bs then C
    const int m0 = blockIdx.x * BM;
    const int n0 = blockIdx.y * BN;
    const int tid = threadIdx.x;

    tf32_mainloop(A, g_w1, N1, m0, n0, smem);

    // Epilogue: 2048 float4s across 256 threads
    #pragma unroll
    for (int it = 0; it < 8; it++) {
        int idx = tid + it * 256;
        int mm = idx >> 4, n4 = idx & 15;
        int c = n0 + n4 * 4;
        if (c >= N1) continue;
        int m = m0 + mm;
        int b = m >> 12, q = m & 4095;
        float4 v = *(float4*)&smem[mm * LDC + n4 * 4];
        v.x += g_b1[c];     v.y += g_b1[c + 1];
        v.z += g_b1[c + 2]; v.w += g_b1[c + 3];
        if (c < 256) {
            int h = c >> 5, d = c & 31;
            *(float4*)&g_val[((((size_t)b << 3) + h) * NQ + q) * HD + d] = v;
        } else if (c < 320) {
            *(float4*)&g_off[(size_t)m * 64 + (c - 256)] = v;
        } else {
            *(float4*)&g_attn[(size_t)m * 32 + (c - 320)] = v;
        }
    }
}

// ---------------------------------------------------------------------------
// GEMM2: g_samp[M,256] @ out_w^T[256,256] + out_b + 2*query -> out
// ---------------------------------------------------------------------------
__global__ __launch_bounds__(256) void gemm2_tc(const float* __restrict__ W,
                                                const float* __restrict__ bias,
                                                const float* __restrict__ query,
                                                float* __restrict__ out) {
    __shared__ float smem[BM * LDC];
    const int m0 = blockIdx.x * BM;
    const int n0 = blockIdx.y * BN;
    const int tid = threadIdx.x;

    tf32_mainloop(g_samp, W, E, m0, n0, smem);

    #pragma unroll
    for (int it = 0; it < 8; it++) {
        int idx = tid + it * 256;
        int mm = idx >> 4, n4 = idx & 15;
        int c = n0 + n4 * 4;
        size_t go = (size_t)(m0 + mm) * E + c;
        float4 v = *(float4*)&smem[mm * LDC + n4 * 4];
        float4 bi = *(const float4*)&bias[c];
        float4 qv = *(const float4*)&query[go];
        v.x += bi.x + 2.0f * qv.x;
        v.y += bi.y + 2.0f * qv.y;
        v.z += bi.z + 2.0f * qv.z;
        v.w += bi.w + 2.0f * qv.w;
        *(float4*)&out[go] = v;
    }
}

// ---------------------------------------------------------------------------
// Sampling: one warp per (m, h); lane = channel d.
// ---------------------------------------------------------------------------
__global__ __launch_bounds__(256) void sample_kernel() {
    const int gid  = blockIdx.x * 8 + (threadIdx.x >> 5);
    const int lane = threadIdx.x & 31;
    const int m = gid >> 3;
    const int h = gid & 7;
    const int b = m >> 12;
    const int q = m & 4095;

    const float* __restrict__ offp = g_off  + (size_t)m * 64 + h * 8;
    const float* __restrict__ attp = g_attn + (size_t)m * 32 + h * 4;

    float a0 = attp[0], a1 = attp[1], a2 = attp[2], a3 = attp[3];
    float mx = fmaxf(fmaxf(a0, a1), fmaxf(a2, a3));
    float e0 = __expf(a0 - mx), e1 = __expf(a1 - mx),
          e2 = __expf(a2 - mx), e3 = __expf(a3 - mx);
    float inv = 1.f / (e0 + e1 + e2 + e3);
    float aw[4] = {e0 * inv, e1 * inv, e2 * inv, e3 * inv};

    const float refx = (float)(q & 63) * (1.0f / 63.0f);
    const float refy = (float)(q >> 6) * (1.0f / 63.0f);
    const float* __restrict__ vp = g_val + (size_t)((b << 3) + h) * NQ * HD;

    float acc = 0.f;
    #pragma unroll
    for (int p = 0; p < NP; p++) {
        float px = refx * 64.0f + offp[2 * p]     - 0.5f;
        float py = refy * 64.0f + offp[2 * p + 1] - 0.5f;
        float fx = floorf(px), fy = floorf(py);
        float wx = px - fx, wy = py - fy;
        int x0 = (int)fx, y0 = (int)fy;
        float s = 0.f;
        #pragma unroll
        for (int dy = 0; dy < 2; dy++) {
            #pragma unroll
            for (int dx = 0; dx < 2; dx++) {
                int xi = x0 + dx, yi = y0 + dy;
                if (xi >= 0 && xi < WW && yi >= 0 && yi < HH) {
                    float cw = (dx ? wx : 1.f - wx) * (dy ? wy : 1.f - wy);
                    s = fmaf(cw, vp[(yi * WW + xi) * HD + lane], s);
                }
            }
        }
        acc = fmaf(aw[p], s, acc);
    }
    g_samp[(size_t)m * E + h * HD + lane] = acc;
}

// ---------------------------------------------------------------------------
extern "C" void kernel_launch(void* const* d_in, const int* in_sizes, int n_in,
                              void* d_out, int out_size) {
    const float* query   = (const float*)d_in[0];
    const float* value_w = (const float*)d_in[1];
    const float* value_b = (const float*)d_in[2];
    const float* off_w   = (const float*)d_in[3];
    const float* off_b   = (const float*)d_in[4];
    const float* attn_w  = (const float*)d_in[5];
    const float* attn_b  = (const float*)d_in[6];
    const float* out_w   = (const float*)d_in[7];
    const float* out_b   = (const float*)d_in[8];
    float* out = (float*)d_out;

    prep_kernel<<<(N1 * E + 255) / 256, 256>>>(value_w, value_b, off_w, off_b, attn_w, attn_b);

    dim3 g1(M_TOT / BM, (N1 + BN - 1) / BN);   // 256 x 6
    gemm1_tc<<<g1, 256>>>(query);

    sample_kernel<<<(M_TOT * NH) / 8, 256>>>();

    dim3 g2(M_TOT / BM, E / BN);               // 256 x 4
    gemm2_tc<<<g2, 256>>>(out_w, out_b, query, out);
}

// round 6
// speedup vs baseline: 2.4349x; 1.6444x over previous
#include <cuda_runtime.h>
#include <cuda_bf16.h>
#include <mma.h>
#include <math.h>

using namespace nvcuda;

// Problem constants
#define BS   8
#define NQ   4096          // 64*64
#define E    256
#define NH   8
#define NP   4
#define HD   32            // E/NH
#define HH   64
#define WW   64
#define M_TOT (BS*NQ)      // 32768
#define N1   352           // 256 (value) + 64 (off) + 32 (attn)

// GEMM tiling
#define BM   128
#define BN   64
#define BK   32
#define LDAH 40            // bf16 leading dim (80 B rows; mult of 8 elems & 16 B)
#define LDC  72            // float C staging leading dim
#define NKT  (E/BK)        // 8 k-tiles
#define STAGE ((BM+BN)*LDAH)   // bf16 elems per pipeline stage (7680)
#define SMEM_BYTES 36864   // max(2*STAGE*2, BM*LDC*4)

// Scratch (device globals)
__device__ __nv_bfloat16 g_val [BS*NH*NQ*HD];  // [b,h,pos,d] bf16
__device__ float         g_off [M_TOT*64];
__device__ float         g_attn[M_TOT*32];
__device__ __nv_bfloat16 g_samp[M_TOT*E];      // [m, h*32+d] bf16
__device__ __nv_bfloat16 g_w1  [N1*E];         // concat proj weights, bf16
__device__ __nv_bfloat16 g_w2  [E*E];          // out_w, bf16
__device__ float         g_b1  [N1];

// ---------------------------------------------------------------------------
// Prep: convert + concat weights to bf16, copy biases
// ---------------------------------------------------------------------------
__global__ void prep_kernel(const float* __restrict__ vw, const float* __restrict__ vb,
                            const float* __restrict__ ow, const float* __restrict__ ob,
                            const float* __restrict__ aw, const float* __restrict__ ab,
                            const float* __restrict__ outw) {
    int i = blockIdx.x * 256 + threadIdx.x;
    if (i < 256*256)      g_w1[i] = __float2bfloat16(vw[i]);
    else if (i < 320*256) g_w1[i] = __float2bfloat16(ow[i - 256*256]);
    else if (i < 352*256) g_w1[i] = __float2bfloat16(aw[i - 320*256]);
    if (i < 256*256)      g_w2[i] = __float2bfloat16(outw[i]);
    if (i < 256)          g_b1[i] = vb[i];
    else if (i < 320)     g_b1[i] = ob[i - 256];
    else if (i < 352)     g_b1[i] = ab[i - 320];
}

// ---------------------------------------------------------------------------
// bf16 pipelined mainloop: C[BM][BN] = A[m0:,:] @ B[n0:,:]^T staged to smem.
// A: fp32 (converted on the fly) or bf16; B: bf16 weights [b_rows,256].
// ---------------------------------------------------------------------------
template<bool A_IS_BF16>
__device__ __forceinline__ void bf16_mainloop(
    const void* __restrict__ Aptr, const __nv_bfloat16* __restrict__ Bsrc,
    int b_rows, int m0, int n0, unsigned char* smem_raw)
{
    __nv_bfloat16* buf = (__nv_bfloat16*)smem_raw;
    const int tid  = threadIdx.x;
    const int warp = tid >> 5;
    const int wr   = warp >> 1;    // 0..3
    const int wc   = warp & 1;     // 0..1

    wmma::fragment<wmma::accumulator, 16, 16, 16, float> c[2][2];
    #pragma unroll
    for (int i = 0; i < 2; i++)
        #pragma unroll
        for (int j = 0; j < 2; j++) wmma::fill_fragment(c[i][j], 0.0f);

    // register staging for next tile
    float          a_regf[2][8];
    __nv_bfloat16  a_regh[2][8];
    __nv_bfloat16  b_regh[8];

    auto load_global = [&](int k0) {
        #pragma unroll
        for (int it = 0; it < 2; it++) {
            int idx = tid + it * 256;
            int row = idx >> 2, cg = idx & 3;       // 128 rows x 4 groups of 8
            if (A_IS_BF16) {
                const __nv_bfloat16* A = (const __nv_bfloat16*)Aptr;
                *(uint4*)a_regh[it] = *(const uint4*)&A[(size_t)(m0 + row) * E + k0 + cg * 8];
            } else {
                const float* A = (const float*)Aptr;
                *(float4*)&a_regf[it][0] = *(const float4*)&A[(size_t)(m0 + row) * E + k0 + cg * 8];
                *(float4*)&a_regf[it][4] = *(const float4*)&A[(size_t)(m0 + row) * E + k0 + cg * 8 + 4];
            }
        }
        {
            int row = tid >> 2, cg = tid & 3;       // 64 rows x 4 groups
            int gn = n0 + row;
            if (gn < b_rows) {
                *(uint4*)b_regh = *(const uint4*)&Bsrc[(size_t)gn * E + k0 + cg * 8];
            } else {
                #pragma unroll
                for (int j = 0; j < 8; j++) b_regh[j] = __float2bfloat16(0.f);
            }
        }
    };

    auto store_stage = [&](int s) {
        __nv_bfloat16* As = buf + s * STAGE;
        __nv_bfloat16* Bs = As + BM * LDAH;
        #pragma unroll
        for (int it = 0; it < 2; it++) {
            int idx = tid + it * 256;
            int row = idx >> 2, cg = idx & 3;
            if (A_IS_BF16) {
                *(uint4*)&As[row * LDAH + cg * 8] = *(uint4*)a_regh[it];
            } else {
                __nv_bfloat16 t[8];
                #pragma unroll
                for (int j = 0; j < 8; j++) t[j] = __float2bfloat16(a_regf[it][j]);
                *(uint4*)&As[row * LDAH + cg * 8] = *(uint4*)t;
            }
        }
        {
            int row = tid >> 2, cg = tid & 3;
            *(uint4*)&Bs[row * LDAH + cg * 8] = *(uint4*)b_regh;
        }
    };

    auto compute = [&](int s) {
        __nv_bfloat16* As = buf + s * STAGE;
        __nv_bfloat16* Bs = As + BM * LDAH;
        #pragma unroll
        for (int kk = 0; kk < BK; kk += 16) {
            wmma::fragment<wmma::matrix_a, 16, 16, 16, __nv_bfloat16, wmma::row_major> a[2];
            wmma::fragment<wmma::matrix_b, 16, 16, 16, __nv_bfloat16, wmma::col_major> b[2];
            #pragma unroll
            for (int i = 0; i < 2; i++)
                wmma::load_matrix_sync(a[i], &As[(wr * 32 + i * 16) * LDAH + kk], LDAH);
            #pragma unroll
            for (int j = 0; j < 2; j++)
                wmma::load_matrix_sync(b[j], &Bs[(wc * 32 + j * 16) * LDAH + kk], LDAH);
            #pragma unroll
            for (int i = 0; i < 2; i++)
                #pragma unroll
                for (int j = 0; j < 2; j++)
                    wmma::mma_sync(c[i][j], a[i], b[j], c[i][j]);
        }
    };

    load_global(0);
    store_stage(0);
    __syncthreads();

    for (int kt = 0; kt < NKT; kt++) {
        if (kt + 1 < NKT) load_global((kt + 1) * BK);
        compute(kt & 1);
        if (kt + 1 < NKT) {
            store_stage((kt + 1) & 1);
            __syncthreads();
        }
    }

    // Stage C in float smem (reuses pipeline buffers)
    __syncthreads();
    float* Cs = (float*)smem_raw;
    #pragma unroll
    for (int i = 0; i < 2; i++)
        #pragma unroll
        for (int j = 0; j < 2; j++)
            wmma::store_matrix_sync(&Cs[(wr * 32 + i * 16) * LDC + wc * 32 + j * 16],
                                    c[i][j], LDC, wmma::mem_row_major);
    __syncthreads();
}

// ---------------------------------------------------------------------------
// GEMM1: query fp32 @ g_w1^T (+bias) -> scatter {g_val bf16, g_off, g_attn}
// ---------------------------------------------------------------------------
__global__ __launch_bounds__(256) void gemm1_tc(const float* __restrict__ A) {
    __shared__ __align__(16) unsigned char smem_raw[SMEM_BYTES];
    const int m0 = blockIdx.x * BM;
    const int n0 = blockIdx.y * BN;
    const int tid = threadIdx.x;

    bf16_mainloop<false>(A, g_w1, N1, m0, n0, smem_raw);
    float* Cs = (float*)smem_raw;

    #pragma unroll
    for (int it = 0; it < 8; it++) {
        int idx = tid + it * 256;
        int mm = idx >> 4, n4 = idx & 15;
        int c = n0 + n4 * 4;
        if (c >= N1) continue;
        int m = m0 + mm;
        int b = m >> 12, q = m & 4095;
        float4 v = *(float4*)&Cs[mm * LDC + n4 * 4];
        v.x += g_b1[c];     v.y += g_b1[c + 1];
        v.z += g_b1[c + 2]; v.w += g_b1[c + 3];
        if (c < 256) {
            int h = c >> 5, d = c & 31;
            __nv_bfloat16 t[4] = {__float2bfloat16(v.x), __float2bfloat16(v.y),
                                  __float2bfloat16(v.z), __float2bfloat16(v.w)};
            *(uint2*)&g_val[((((size_t)b << 3) + h) * NQ + q) * HD + d] = *(uint2*)t;
        } else if (c < 320) {
            *(float4*)&g_off[(size_t)m * 64 + (c - 256)] = v;
        } else {
            *(float4*)&g_attn[(size_t)m * 32 + (c - 320)] = v;
        }
    }
}

// ---------------------------------------------------------------------------
// GEMM2: g_samp bf16 @ g_w2^T + out_b + 2*query -> out (fp32)
// ---------------------------------------------------------------------------
__global__ __launch_bounds__(256) void gemm2_tc(const float* __restrict__ bias,
                                                const float* __restrict__ query,
                                                float* __restrict__ out) {
    __shared__ __align__(16) unsigned char smem_raw[SMEM_BYTES];
    const int m0 = blockIdx.x * BM;
    const int n0 = blockIdx.y * BN;
    const int tid = threadIdx.x;

    bf16_mainloop<true>(g_samp, g_w2, E, m0, n0, smem_raw);
    float* Cs = (float*)smem_raw;

    #pragma unroll
    for (int it = 0; it < 8; it++) {
        int idx = tid + it * 256;
        int mm = idx >> 4, n4 = idx & 15;
        int c = n0 + n4 * 4;
        size_t go = (size_t)(m0 + mm) * E + c;
        float4 v = *(float4*)&Cs[mm * LDC + n4 * 4];
        float4 bi = *(const float4*)&bias[c];
        float4 qv = *(const float4*)&query[go];
        v.x += bi.x + 2.0f * qv.x;
        v.y += bi.y + 2.0f * qv.y;
        v.z += bi.z + 2.0f * qv.z;
        v.w += bi.w + 2.0f * qv.w;
        *(float4*)&out[go] = v;
    }
}

// ---------------------------------------------------------------------------
// Sampling: one warp per (m, h); lane = channel d. bf16 value gathers.
// ---------------------------------------------------------------------------
__global__ __launch_bounds__(256) void sample_kernel() {
    const int gid  = blockIdx.x * 8 + (threadIdx.x >> 5);
    const int lane = threadIdx.x & 31;
    const int m = gid >> 3;
    const int h = gid & 7;
    const int b = m >> 12;
    const int q = m & 4095;

    const float* __restrict__ offp = g_off  + (size_t)m * 64 + h * 8;
    const float* __restrict__ attp = g_attn + (size_t)m * 32 + h * 4;

    float a0 = attp[0], a1 = attp[1], a2 = attp[2], a3 = attp[3];
    float mx = fmaxf(fmaxf(a0, a1), fmaxf(a2, a3));
    float e0 = __expf(a0 - mx), e1 = __expf(a1 - mx),
          e2 = __expf(a2 - mx), e3 = __expf(a3 - mx);
    float inv = 1.f / (e0 + e1 + e2 + e3);
    float aw[4] = {e0 * inv, e1 * inv, e2 * inv, e3 * inv};

    const float refx = (float)(q & 63) * (1.0f / 63.0f);
    const float refy = (float)(q >> 6) * (1.0f / 63.0f);
    const __nv_bfloat16* __restrict__ vp = g_val + (size_t)((b << 3) + h) * NQ * HD;

    float acc = 0.f;
    #pragma unroll
    for (int p = 0; p < NP; p++) {
        float px = refx * 64.0f + offp[2 * p]     - 0.5f;
        float py = refy * 64.0f + offp[2 * p + 1] - 0.5f;
        float fx = floorf(px), fy = floorf(py);
        float wx = px - fx, wy = py - fy;
        int x0 = (int)fx, y0 = (int)fy;
        float s = 0.f;
        #pragma unroll
        for (int dy = 0; dy < 2; dy++) {
            #pragma unroll
            for (int dx = 0; dx < 2; dx++) {
                int xi = x0 + dx, yi = y0 + dy;
                if (xi >= 0 && xi < WW && yi >= 0 && yi < HH) {
                    float cw = (dx ? wx : 1.f - wx) * (dy ? wy : 1.f - wy);
                    s = fmaf(cw, __bfloat162float(vp[(yi * WW + xi) * HD + lane]), s);
                }
            }
        }
        acc = fmaf(aw[p], s, acc);
    }
    g_samp[(size_t)m * E + h * HD + lane] = __float2bfloat16(acc);
}

// ---------------------------------------------------------------------------
extern "C" void kernel_launch(void* const* d_in, const int* in_sizes, int n_in,
                              void* d_out, int out_size) {
    const float* query   = (const float*)d_in[0];
    const float* value_w = (const float*)d_in[1];
    const float* value_b = (const float*)d_in[2];
    const float* off_w   = (const float*)d_in[3];
    const float* off_b   = (const float*)d_in[4];
    const float* attn_w  = (const float*)d_in[5];
    const float* attn_b  = (const float*)d_in[6];
    const float* out_w   = (const float*)d_in[7];
    const float* out_b   = (const float*)d_in[8];
    float* out = (float*)d_out;

    prep_kernel<<<(N1 * E + 255) / 256, 256>>>(value_w, value_b, off_w, off_b,
                                               attn_w, attn_b, out_w);

    dim3 g1(M_TOT / BM, (N1 + BN - 1) / BN);   // 256 x 6
    gemm1_tc<<<g1, 256>>>(query);

    sample_kernel<<<(M_TOT * NH) / 8, 256>>>();

    dim3 g2(M_TOT / BM, E / BN);               // 256 x 4
    gemm2_tc<<<g2, 256>>>(out_b, query, out);
}

// round 7
// speedup vs baseline: 2.9614x; 1.2162x over previous
#include <cuda_runtime.h>
#include <cuda_bf16.h>
#include <mma.h>
#include <math.h>

using namespace nvcuda;

// Problem constants
#define BS   8
#define NQ   4096
#define E    256
#define NH   8
#define NP   4
#define HD   32
#define HH   64
#define WW   64
#define M_TOT (BS*NQ)      // 32768
#define N1   352

// GEMM tiling
#define BM   128
#define BN   128
#define BK   32
#define LDAH 40                    // bf16 leading dim (80B rows)
#define LDC  136                   // float C staging leading dim
#define NKT  (E/BK)                // 8
#define STAGE ((BM+BN)*LDAH)       // 10240 bf16 per stage
#define DYN_SMEM 69632             // max(2*STAGE*2 = 40960, BM*LDC*4 = 69632)

// Scratch
__device__ __nv_bfloat16 g_qb  [M_TOT*E];      // query bf16
__device__ __nv_bfloat16 g_val [BS*NH*NQ*HD];  // [b,h,pos,d]
__device__ float         g_off [M_TOT*64];
__device__ float         g_attn[M_TOT*32];
__device__ __nv_bfloat16 g_samp[M_TOT*E];
__device__ __nv_bfloat16 g_w1  [N1*E];
__device__ __nv_bfloat16 g_w2  [E*E];
__device__ float         g_b1  [N1];

// ---------------------------------------------------------------------------
__device__ __forceinline__ void cp_async16(void* sdst, const void* gsrc) {
    unsigned s = (unsigned)__cvta_generic_to_shared(sdst);
    asm volatile("cp.async.cg.shared.global [%0], [%1], 16;\n" :: "r"(s), "l"(gsrc));
}

// ---------------------------------------------------------------------------
// Prep: weights -> bf16 (concat), biases
// ---------------------------------------------------------------------------
__global__ void prep_w(const float* __restrict__ vw, const float* __restrict__ vb,
                       const float* __restrict__ ow, const float* __restrict__ ob,
                       const float* __restrict__ aw, const float* __restrict__ ab,
                       const float* __restrict__ outw) {
    int i = blockIdx.x * 256 + threadIdx.x;
    if (i < 256*256)      g_w1[i] = __float2bfloat16(vw[i]);
    else if (i < 320*256) g_w1[i] = __float2bfloat16(ow[i - 256*256]);
    else if (i < 352*256) g_w1[i] = __float2bfloat16(aw[i - 320*256]);
    if (i < 256*256)      g_w2[i] = __float2bfloat16(outw[i]);
    if (i < 256)          g_b1[i] = vb[i];
    else if (i < 320)     g_b1[i] = ob[i - 256];
    else if (i < 352)     g_b1[i] = ab[i - 320];
}

// query fp32 -> bf16, 8 elems/thread
__global__ void prep_q(const float* __restrict__ qsrc) {
    int i = (blockIdx.x * 256 + threadIdx.x) * 8;
    float4 u = *(const float4*)&qsrc[i];
    float4 v = *(const float4*)&qsrc[i + 4];
    __nv_bfloat16 t[8] = {
        __float2bfloat16(u.x), __float2bfloat16(u.y),
        __float2bfloat16(u.z), __float2bfloat16(u.w),
        __float2bfloat16(v.x), __float2bfloat16(v.y),
        __float2bfloat16(v.z), __float2bfloat16(v.w)};
    *(uint4*)&g_qb[i] = *(uint4*)t;
}

// ---------------------------------------------------------------------------
// bf16 cp.async pipelined mainloop: C[BM][BN] = A @ B^T staged to smem (fp32).
// ---------------------------------------------------------------------------
__device__ __forceinline__ void bf16_mainloop(
    const __nv_bfloat16* __restrict__ A, const __nv_bfloat16* __restrict__ B,
    int b_rows, int m0, int n0, unsigned char* smem_raw)
{
    __nv_bfloat16* buf = (__nv_bfloat16*)smem_raw;
    const int tid  = threadIdx.x;
    const int warp = tid >> 5;
    const int wr   = warp >> 2;    // 0..1 -> 64-row block
    const int wc   = warp & 3;     // 0..3 -> 32-col block

    wmma::fragment<wmma::accumulator, 16, 16, 16, float> c[4][2];
    #pragma unroll
    for (int i = 0; i < 4; i++)
        #pragma unroll
        for (int j = 0; j < 2; j++) wmma::fill_fragment(c[i][j], 0.0f);

    auto issue = [&](int s, int k0) {
        __nv_bfloat16* St = buf + s * STAGE;
        #pragma unroll
        for (int it = 0; it < 4; it++) {
            int idx = tid + it * 256;        // 0..1023
            int row = idx >> 2, cg = idx & 3;
            const __nv_bfloat16* src;
            if (row < BM) {
                src = A + (size_t)(m0 + row) * E + k0 + cg * 8;
            } else {
                int gn = n0 + row - BM;
                if (gn >= b_rows) gn = b_rows - 1;   // clamp; junk cols skipped in epilogue
                src = B + (size_t)gn * E + k0 + cg * 8;
            }
            cp_async16(St + row * LDAH + cg * 8, src);
        }
        asm volatile("cp.async.commit_group;\n" ::);
    };

    auto compute = [&](int s) {
        __nv_bfloat16* As = buf + s * STAGE;
        __nv_bfloat16* Bs = As + BM * LDAH;
        #pragma unroll
        for (int kk = 0; kk < BK; kk += 16) {
            wmma::fragment<wmma::matrix_a, 16, 16, 16, __nv_bfloat16, wmma::row_major> a[4];
            wmma::fragment<wmma::matrix_b, 16, 16, 16, __nv_bfloat16, wmma::col_major> b[2];
            #pragma unroll
            for (int i = 0; i < 4; i++)
                wmma::load_matrix_sync(a[i], &As[(wr * 64 + i * 16) * LDAH + kk], LDAH);
            #pragma unroll
            for (int j = 0; j < 2; j++)
                wmma::load_matrix_sync(b[j], &Bs[(wc * 32 + j * 16) * LDAH + kk], LDAH);
            #pragma unroll
            for (int i = 0; i < 4; i++)
                #pragma unroll
                for (int j = 0; j < 2; j++)
                    wmma::mma_sync(c[i][j], a[i], b[j], c[i][j]);
        }
    };

    issue(0, 0);
    for (int kt = 0; kt < NKT; kt++) {
        if (kt + 1 < NKT) {
            issue((kt + 1) & 1, (kt + 1) * BK);
            asm volatile("cp.async.wait_group 1;\n" ::);
        } else {
            asm volatile("cp.async.wait_group 0;\n" ::);
        }
        __syncthreads();
        compute(kt & 1);
        __syncthreads();
    }

    float* Cs = (float*)smem_raw;
    #pragma unroll
    for (int i = 0; i < 4; i++)
        #pragma unroll
        for (int j = 0; j < 2; j++)
            wmma::store_matrix_sync(&Cs[(wr * 64 + i * 16) * LDC + wc * 32 + j * 16],
                                    c[i][j], LDC, wmma::mem_row_major);
    __syncthreads();
}

// ---------------------------------------------------------------------------
// GEMM1: g_qb @ g_w1^T (+bias) -> scatter {g_val bf16, g_off, g_attn}
// ---------------------------------------------------------------------------
__global__ __launch_bounds__(256) void gemm1_tc() {
    extern __shared__ unsigned char smem_raw[];
    const int m0 = blockIdx.x * BM;
    const int n0 = blockIdx.y * BN;
    const int tid = threadIdx.x;

    bf16_mainloop(g_qb, g_w1, N1, m0, n0, smem_raw);
    float* Cs = (float*)smem_raw;

    #pragma unroll
    for (int it = 0; it < 16; it++) {
        int idx = tid + it * 256;
        int mm = idx >> 5, n4 = idx & 31;
        int c = n0 + n4 * 4;
        if (c >= N1) continue;
        int m = m0 + mm;
        int b = m >> 12, q = m & 4095;
        float4 v = *(float4*)&Cs[mm * LDC + n4 * 4];
        v.x += g_b1[c];     v.y += g_b1[c + 1];
        v.z += g_b1[c + 2]; v.w += g_b1[c + 3];
        if (c < 256) {
            int h = c >> 5, d = c & 31;
            __nv_bfloat16 t[4] = {__float2bfloat16(v.x), __float2bfloat16(v.y),
                                  __float2bfloat16(v.z), __float2bfloat16(v.w)};
            *(uint2*)&g_val[((((size_t)b << 3) + h) * NQ + q) * HD + d] = *(uint2*)t;
        } else if (c < 320) {
            *(float4*)&g_off[(size_t)m * 64 + (c - 256)] = v;
        } else {
            *(float4*)&g_attn[(size_t)m * 32 + (c - 320)] = v;
        }
    }
}

// ---------------------------------------------------------------------------
// GEMM2: g_samp @ g_w2^T + out_b + 2*query -> out
// ---------------------------------------------------------------------------
__global__ __launch_bounds__(256) void gemm2_tc(const float* __restrict__ bias,
                                                const float* __restrict__ query,
                                                float* __restrict__ out) {
    extern __shared__ unsigned char smem_raw[];
    const int m0 = blockIdx.x * BM;
    const int n0 = blockIdx.y * BN;
    const int tid = threadIdx.x;

    bf16_mainloop(g_samp, g_w2, E, m0, n0, smem_raw);
    float* Cs = (float*)smem_raw;

    #pragma unroll
    for (int it = 0; it < 16; it++) {
        int idx = tid + it * 256;
        int mm = idx >> 5, n4 = idx & 31;
        int c = n0 + n4 * 4;
        size_t go = (size_t)(m0 + mm) * E + c;
        float4 v = *(float4*)&Cs[mm * LDC + n4 * 4];
        float4 bi = *(const float4*)&bias[c];
        float4 qv = *(const float4*)&query[go];
        v.x += bi.x + 2.0f * qv.x;
        v.y += bi.y + 2.0f * qv.y;
        v.z += bi.z + 2.0f * qv.z;
        v.w += bi.w + 2.0f * qv.w;
        *(float4*)&out[go] = v;
    }
}

// ---------------------------------------------------------------------------
// Sampling: block = query m, warp = head h.
// Within a warp: point p = lane>>3 (4 points parallel), channel group cg = lane&7
// (4 channels each). Gathers are uint2 (4 bf16). Cross-point reduce via shfl.
// ---------------------------------------------------------------------------
__global__ __launch_bounds__(256) void sample_kernel() {
    const int m    = blockIdx.x;
    const int h    = threadIdx.x >> 5;
    const int lane = threadIdx.x & 31;
    const int p    = lane >> 3;
    const int cg   = lane & 7;
    const int b = m >> 12;
    const int q = m & 4095;

    const float2 off = *(const float2*)&g_off[(size_t)m * 64 + h * 8 + p * 2];
    const float4 at  = *(const float4*)&g_attn[(size_t)m * 32 + h * 4];

    float mx = fmaxf(fmaxf(at.x, at.y), fmaxf(at.z, at.w));
    float e0 = __expf(at.x - mx), e1 = __expf(at.y - mx),
          e2 = __expf(at.z - mx), e3 = __expf(at.w - mx);
    float inv = 1.f / (e0 + e1 + e2 + e3);
    float awp = (p == 0 ? e0 : p == 1 ? e1 : p == 2 ? e2 : e3) * inv;

    const float px = (float)(q & 63) * (64.0f / 63.0f) + off.x - 0.5f;
    const float py = (float)(q >> 6) * (64.0f / 63.0f) + off.y - 0.5f;
    const float fx = floorf(px), fy = floorf(py);
    const float wx = px - fx, wy = py - fy;
    const int x0 = (int)fx, y0 = (int)fy;

    const __nv_bfloat16* __restrict__ vp =
        g_val + (((size_t)(b << 3) + h) * NQ) * HD + cg * 4;

    float4 acc = make_float4(0.f, 0.f, 0.f, 0.f);
    #pragma unroll
    for (int dy = 0; dy < 2; dy++) {
        #pragma unroll
        for (int dx = 0; dx < 2; dx++) {
            int xi = x0 + dx, yi = y0 + dy;
            if (xi >= 0 && xi < WW && yi >= 0 && yi < HH) {
                float cw = (dx ? wx : 1.f - wx) * (dy ? wy : 1.f - wy);
                const __nv_bfloat162* pv =
                    (const __nv_bfloat162*)(vp + (yi * WW + xi) * HD);
                __nv_bfloat162 r0 = pv[0], r1 = pv[1];
                float2 f0 = __bfloat1622float2(r0);
                float2 f1 = __bfloat1622float2(r1);
                acc.x = fmaf(cw, f0.x, acc.x);
                acc.y = fmaf(cw, f0.y, acc.y);
                acc.z = fmaf(cw, f1.x, acc.z);
                acc.w = fmaf(cw, f1.y, acc.w);
            }
        }
    }
    acc.x *= awp; acc.y *= awp; acc.z *= awp; acc.w *= awp;

    // reduce across the 4 point-groups (lanes differing in bits 3,4)
    #pragma unroll
    for (int msk = 8; msk <= 16; msk <<= 1) {
        acc.x += __shfl_xor_sync(0xFFFFFFFF, acc.x, msk);
        acc.y += __shfl_xor_sync(0xFFFFFFFF, acc.y, msk);
        acc.z += __shfl_xor_sync(0xFFFFFFFF, acc.z, msk);
        acc.w += __shfl_xor_sync(0xFFFFFFFF, acc.w, msk);
    }

    if (lane < 8) {
        __nv_bfloat16 t[4] = {__float2bfloat16(acc.x), __float2bfloat16(acc.y),
                              __float2bfloat16(acc.z), __float2bfloat16(acc.w)};
        *(uint2*)&g_samp[(size_t)m * E + h * HD + cg * 4] = *(uint2*)t;
    }
}

// ---------------------------------------------------------------------------
extern "C" void kernel_launch(void* const* d_in, const int* in_sizes, int n_in,
                              void* d_out, int out_size) {
    const float* query   = (const float*)d_in[0];
    const float* value_w = (const float*)d_in[1];
    const float* value_b = (const float*)d_in[2];
    const float* off_w   = (const float*)d_in[3];
    const float* off_b   = (const float*)d_in[4];
    const float* attn_w  = (const float*)d_in[5];
    const float* attn_b  = (const float*)d_in[6];
    const float* out_w   = (const float*)d_in[7];
    const float* out_b   = (const float*)d_in[8];
    float* out = (float*)d_out;

    static bool attr_done = false;
    if (!attr_done) {
        cudaFuncSetAttribute(gemm1_tc, cudaFuncAttributeMaxDynamicSharedMemorySize, DYN_SMEM);
        cudaFuncSetAttribute(gemm2_tc, cudaFuncAttributeMaxDynamicSharedMemorySize, DYN_SMEM);
        attr_done = true;
    }

    prep_w<<<(N1 * E + 255) / 256, 256>>>(value_w, value_b, off_w, off_b,
                                          attn_w, attn_b, out_w);
    prep_q<<<(M_TOT * E) / (256 * 8), 256>>>(query);

    dim3 g1(M_TOT / BM, (N1 + BN - 1) / BN);   // 256 x 3
    gemm1_tc<<<g1, 256, DYN_SMEM>>>();

    sample_kernel<<<M_TOT, 256>>>();

    dim3 g2(M_TOT / BM, E / BN);               // 256 x 2
    gemm2_tc<<<g2, 256, DYN_SMEM>>>(out_b, query, out);
}

// round 8
// speedup vs baseline: 3.3722x; 1.1387x over previous
#include <cuda_runtime.h>
#include <cuda_bf16.h>
#include <mma.h>
#include <math.h>

using namespace nvcuda;

// Problem constants
#define BS   8
#define NQ   4096
#define E    256
#define NH   8
#define NP   4
#define HD   32
#define HH   64
#define WW   64
#define M_TOT (BS*NQ)      // 32768
#define N1   352

// GEMM tiling
#define BM   128
#define BN   128
#define BK   32
#define LDAH 40                    // bf16 leading dim (80B rows)
#define LDC  136                   // float C staging leading dim
#define NKT  (E/BK)                // 8
#define STAGE ((BM+BN)*LDAH)       // 10240 bf16 per stage
#define DYN_SMEM 69632             // max(2*STAGE*2 = 40960, BM*LDC*4 = 69632)

// Scratch
__device__ __nv_bfloat16 g_qb  [M_TOT*E];      // query bf16
__device__ __nv_bfloat16 g_val [BS*NH*NQ*HD];  // [b,h,pos,d]
__device__ float         g_off [M_TOT*64];
__device__ float         g_attn[M_TOT*32];
__device__ __nv_bfloat16 g_samp[M_TOT*E];
__device__ __nv_bfloat16 g_w1  [N1*E];
__device__ __nv_bfloat16 g_w2  [E*E];
__device__ float         g_b1  [N1];

// ---------------------------------------------------------------------------
__device__ __forceinline__ void cp_async16(void* sdst, const void* gsrc) {
    unsigned s = (unsigned)__cvta_generic_to_shared(sdst);
    asm volatile("cp.async.cg.shared.global [%0], [%1], 16;\n" :: "r"(s), "l"(gsrc));
}

// ---------------------------------------------------------------------------
// Prep: weights -> bf16 (concat), biases
// ---------------------------------------------------------------------------
__global__ void prep_w(const float* __restrict__ vw, const float* __restrict__ vb,
                       const float* __restrict__ ow, const float* __restrict__ ob,
                       const float* __restrict__ aw, const float* __restrict__ ab,
                       const float* __restrict__ outw) {
    int i = blockIdx.x * 256 + threadIdx.x;
    if (i < 256*256)      g_w1[i] = __float2bfloat16(vw[i]);
    else if (i < 320*256) g_w1[i] = __float2bfloat16(ow[i - 256*256]);
    else if (i < 352*256) g_w1[i] = __float2bfloat16(aw[i - 320*256]);
    if (i < 256*256)      g_w2[i] = __float2bfloat16(outw[i]);
    if (i < 256)          g_b1[i] = vb[i];
    else if (i < 320)     g_b1[i] = ob[i - 256];
    else if (i < 352)     g_b1[i] = ab[i - 320];
}

// query fp32 -> bf16, 8 elems/thread
__global__ void prep_q(const float* __restrict__ qsrc) {
    int i = (blockIdx.x * 256 + threadIdx.x) * 8;
    float4 u = *(const float4*)&qsrc[i];
    float4 v = *(const float4*)&qsrc[i + 4];
    __nv_bfloat16 t[8] = {
        __float2bfloat16(u.x), __float2bfloat16(u.y),
        __float2bfloat16(u.z), __float2bfloat16(u.w),
        __float2bfloat16(v.x), __float2bfloat16(v.y),
        __float2bfloat16(v.z), __float2bfloat16(v.w)};
    *(uint4*)&g_qb[i] = *(uint4*)t;
}

// ---------------------------------------------------------------------------
// bf16 cp.async pipelined mainloop: C[BM][BN] = A @ B^T staged to smem (fp32).
// ---------------------------------------------------------------------------
__device__ __forceinline__ void bf16_mainloop(
    const __nv_bfloat16* __restrict__ A, const __nv_bfloat16* __restrict__ B,
    int b_rows, int m0, int n0, unsigned char* smem_raw)
{
    __nv_bfloat16* buf = (__nv_bfloat16*)smem_raw;
    const int tid  = threadIdx.x;
    const int warp = tid >> 5;
    const int wr   = warp >> 2;    // 0..1 -> 64-row block
    const int wc   = warp & 3;     // 0..3 -> 32-col block

    wmma::fragment<wmma::accumulator, 16, 16, 16, float> c[4][2];
    #pragma unroll
    for (int i = 0; i < 4; i++)
        #pragma unroll
        for (int j = 0; j < 2; j++) wmma::fill_fragment(c[i][j], 0.0f);

    auto issue = [&](int s, int k0) {
        __nv_bfloat16* St = buf + s * STAGE;
        #pragma unroll
        for (int it = 0; it < 4; it++) {
            int idx = tid + it * 256;        // 0..1023
            int row = idx >> 2, cg = idx & 3;
            const __nv_bfloat16* src;
            if (row < BM) {
                src = A + (size_t)(m0 + row) * E + k0 + cg * 8;
            } else {
                int gn = n0 + row - BM;
                if (gn >= b_rows) gn = b_rows - 1;   // clamp; junk cols skipped in epilogue
                src = B + (size_t)gn * E + k0 + cg * 8;
            }
            cp_async16(St + row * LDAH + cg * 8, src);
        }
        asm volatile("cp.async.commit_group;\n" ::);
    };

    auto compute = [&](int s) {
        __nv_bfloat16* As = buf + s * STAGE;
        __nv_bfloat16* Bs = As + BM * LDAH;
        #pragma unroll
        for (int kk = 0; kk < BK; kk += 16) {
            wmma::fragment<wmma::matrix_a, 16, 16, 16, __nv_bfloat16, wmma::row_major> a[4];
            wmma::fragment<wmma::matrix_b, 16, 16, 16, __nv_bfloat16, wmma::col_major> b[2];
            #pragma unroll
            for (int i = 0; i < 4; i++)
                wmma::load_matrix_sync(a[i], &As[(wr * 64 + i * 16) * LDAH + kk], LDAH);
            #pragma unroll
            for (int j = 0; j < 2; j++)
                wmma::load_matrix_sync(b[j], &Bs[(wc * 32 + j * 16) * LDAH + kk], LDAH);
            #pragma unroll
            for (int i = 0; i < 4; i++)
                #pragma unroll
                for (int j = 0; j < 2; j++)
                    wmma::mma_sync(c[i][j], a[i], b[j], c[i][j]);
        }
    };

    issue(0, 0);
    for (int kt = 0; kt < NKT; kt++) {
        if (kt + 1 < NKT) {
            issue((kt + 1) & 1, (kt + 1) * BK);
            asm volatile("cp.async.wait_group 1;\n" ::);
        } else {
            asm volatile("cp.async.wait_group 0;\n" ::);
        }
        __syncthreads();
        compute(kt & 1);
        __syncthreads();
    }

    float* Cs = (float*)smem_raw;
    #pragma unroll
    for (int i = 0; i < 4; i++)
        #pragma unroll
        for (int j = 0; j < 2; j++)
            wmma::store_matrix_sync(&Cs[(wr * 64 + i * 16) * LDC + wc * 32 + j * 16],
                                    c[i][j], LDC, wmma::mem_row_major);
    __syncthreads();
}

// ---------------------------------------------------------------------------
// GEMM1: g_qb @ g_w1^T (+bias) -> scatter {g_val bf16, g_off, g_attn}
// ---------------------------------------------------------------------------
__global__ __launch_bounds__(256) void gemm1_tc() {
    extern __shared__ unsigned char smem_raw[];
    const int m0 = blockIdx.x * BM;
    const int n0 = blockIdx.y * BN;
    const int tid = threadIdx.x;

    bf16_mainloop(g_qb, g_w1, N1, m0, n0, smem_raw);
    float* Cs = (float*)smem_raw;

    #pragma unroll
    for (int it = 0; it < 16; it++) {
        int idx = tid + it * 256;
        int mm = idx >> 5, n4 = idx & 31;
        int c = n0 + n4 * 4;
        if (c >= N1) continue;
        int m = m0 + mm;
        int b = m >> 12, q = m & 4095;
        float4 v = *(float4*)&Cs[mm * LDC + n4 * 4];
        v.x += g_b1[c];     v.y += g_b1[c + 1];
        v.z += g_b1[c + 2]; v.w += g_b1[c + 3];
        if (c < 256) {
            int h = c >> 5, d = c & 31;
            __nv_bfloat16 t[4] = {__float2bfloat16(v.x), __float2bfloat16(v.y),
                                  __float2bfloat16(v.z), __float2bfloat16(v.w)};
            *(uint2*)&g_val[((((size_t)b << 3) + h) * NQ + q) * HD + d] = *(uint2*)t;
        } else if (c < 320) {
            *(float4*)&g_off[(size_t)m * 64 + (c - 256)] = v;
        } else {
            *(float4*)&g_attn[(size_t)m * 32 + (c - 320)] = v;
        }
    }
}

// ---------------------------------------------------------------------------
// GEMM2: g_samp @ g_w2^T + out_b + 2*query -> out
// ---------------------------------------------------------------------------
__global__ __launch_bounds__(256) void gemm2_tc(const float* __restrict__ bias,
                                                const float* __restrict__ query,
                                                float* __restrict__ out) {
    extern __shared__ unsigned char smem_raw[];
    const int m0 = blockIdx.x * BM;
    const int n0 = blockIdx.y * BN;
    const int tid = threadIdx.x;

    bf16_mainloop(g_samp, g_w2, E, m0, n0, smem_raw);
    float* Cs = (float*)smem_raw;

    #pragma unroll
    for (int it = 0; it < 16; it++) {
        int idx = tid + it * 256;
        int mm = idx >> 5, n4 = idx & 31;
        int c = n0 + n4 * 4;
        size_t go = (size_t)(m0 + mm) * E + c;
        float4 v = *(float4*)&Cs[mm * LDC + n4 * 4];
        float4 bi = *(const float4*)&bias[c];
        float4 qv = *(const float4*)&query[go];
        v.x += bi.x + 2.0f * qv.x;
        v.y += bi.y + 2.0f * qv.y;
        v.z += bi.z + 2.0f * qv.z;
        v.w += bi.w + 2.0f * qv.w;
        *(float4*)&out[go] = v;
    }
}

// ---------------------------------------------------------------------------
// Sampling v3: warp covers 2 heads of one query.
//   lane>>4  : which head of the pair
//   (lane>>2)&3 : point p   (4 points in parallel)
//   lane&3   : channel group (8 bf16 via one uint4 gather)
// Validity folded into edge weights (branch-free); attn weight folded into wy.
// Cross-point reduce via shfl-xor (masks 4, 8 — stays inside 16-lane group).
// ---------------------------------------------------------------------------
__global__ __launch_bounds__(256) void sample_kernel() {
    const int wid  = blockIdx.x * 8 + (threadIdx.x >> 5);  // 0 .. M_TOT*4-1
    const int lane = threadIdx.x & 31;
    const int m    = wid >> 2;
    const int h    = ((wid & 3) << 1) + (lane >> 4);       // 0..7
    const int p    = (lane >> 2) & 3;
    const int cg   = lane & 3;
    const int b = m >> 12;
    const int q = m & 4095;

    const float2 off = *(const float2*)&g_off[(size_t)m * 64 + h * 8 + p * 2];
    const float4 at  = *(const float4*)&g_attn[(size_t)m * 32 + h * 4];

    float mx = fmaxf(fmaxf(at.x, at.y), fmaxf(at.z, at.w));
    float e0 = __expf(at.x - mx), e1 = __expf(at.y - mx),
          e2 = __expf(at.z - mx), e3 = __expf(at.w - mx);
    float inv = 1.f / (e0 + e1 + e2 + e3);
    float awp = (p == 0 ? e0 : p == 1 ? e1 : p == 2 ? e2 : e3) * inv;

    const float px = (float)(q & 63) * (64.0f / 63.0f) + off.x - 0.5f;
    const float py = (float)(q >> 6) * (64.0f / 63.0f) + off.y - 0.5f;
    const float fx = floorf(px), fy = floorf(py);
    const float wx = px - fx, wy = py - fy;
    const int ix = (int)fx, iy = (int)fy;

    // validity folded into edge weights; attn weight folded into y-weights
    float wxl = (ix >= 0  && ix < 64) ? (1.f - wx) : 0.f;
    float wxr = (ix >= -1 && ix < 63) ? wx         : 0.f;
    float wyt = ((iy >= 0  && iy < 64) ? (1.f - wy) : 0.f) * awp;
    float wyb = ((iy >= -1 && iy < 63) ? wy         : 0.f) * awp;

    const int ix0 = min(max(ix, 0), 63),     ix1 = min(max(ix + 1, 0), 63);
    const int iy0 = min(max(iy, 0), 63),     iy1 = min(max(iy + 1, 0), 63);
    const int c00 = (iy0 << 11) + (ix0 << 5);
    const int c01 = (iy0 << 11) + (ix1 << 5);
    const int c10 = (iy1 << 11) + (ix0 << 5);
    const int c11 = (iy1 << 11) + (ix1 << 5);
    const float w00 = wxl * wyt, w01 = wxr * wyt;
    const float w10 = wxl * wyb, w11 = wxr * wyb;

    const __nv_bfloat16* __restrict__ vp =
        g_val + (((size_t)(b << 3) + h) * NQ) * HD + (cg << 3);

    float acc[8];
    #pragma unroll
    for (int j = 0; j < 8; j++) acc[j] = 0.f;

    #pragma unroll
    for (int cn = 0; cn < 4; cn++) {
        int  o = (cn == 0 ? c00 : cn == 1 ? c01 : cn == 2 ? c10 : c11);
        float w = (cn == 0 ? w00 : cn == 1 ? w01 : cn == 2 ? w10 : w11);
        uint4 r = *(const uint4*)(vp + o);
        const __nv_bfloat162* h2 = (const __nv_bfloat162*)&r;
        #pragma unroll
        for (int j = 0; j < 4; j++) {
            float2 f = __bfloat1622float2(h2[j]);
            acc[2*j]   = fmaf(w, f.x, acc[2*j]);
            acc[2*j+1] = fmaf(w, f.y, acc[2*j+1]);
        }
    }

    // reduce over the 4 points (lane bits 2,3)
    #pragma unroll
    for (int msk = 4; msk <= 8; msk <<= 1)
        #pragma unroll
        for (int j = 0; j < 8; j++)
            acc[j] += __shfl_xor_sync(0xFFFFFFFF, acc[j], msk);

    if (p == 0) {
        __nv_bfloat16 t[8];
        #pragma unroll
        for (int j = 0; j < 8; j++) t[j] = __float2bfloat16(acc[j]);
        *(uint4*)&g_samp[(size_t)m * E + h * HD + (cg << 3)] = *(uint4*)t;
    }
}

// ---------------------------------------------------------------------------
extern "C" void kernel_launch(void* const* d_in, const int* in_sizes, int n_in,
                              void* d_out, int out_size) {
    const float* query   = (const float*)d_in[0];
    const float* value_w = (const float*)d_in[1];
    const float* value_b = (const float*)d_in[2];
    const float* off_w   = (const float*)d_in[3];
    const float* off_b   = (const float*)d_in[4];
    const float* attn_w  = (const float*)d_in[5];
    const float* attn_b  = (const float*)d_in[6];
    const float* out_w   = (const float*)d_in[7];
    const float* out_b   = (const float*)d_in[8];
    float* out = (float*)d_out;

    static bool attr_done = false;
    if (!attr_done) {
        cudaFuncSetAttribute(gemm1_tc, cudaFuncAttributeMaxDynamicSharedMemorySize, DYN_SMEM);
        cudaFuncSetAttribute(gemm2_tc, cudaFuncAttributeMaxDynamicSharedMemorySize, DYN_SMEM);
        attr_done = true;
    }

    prep_w<<<(N1 * E + 255) / 256, 256>>>(value_w, value_b, off_w, off_b,
                                          attn_w, attn_b, out_w);
    prep_q<<<(M_TOT * E) / (256 * 8), 256>>>(query);

    dim3 g1(M_TOT / BM, (N1 + BN - 1) / BN);   // 256 x 3
    gemm1_tc<<<g1, 256, DYN_SMEM>>>();

    sample_kernel<<<(M_TOT * 4) / 8, 256>>>();

    dim3 g2(M_TOT / BM, E / BN);               // 256 x 2
    gemm2_tc<<<g2, 256, DYN_SMEM>>>(out_b, query, out);
}

// round 10
// speedup vs baseline: 3.4914x; 1.0353x over previous
#include <cuda_runtime.h>
#include <cuda_bf16.h>
#include <mma.h>
#include <math.h>

using namespace nvcuda;

// Problem constants
#define BS   8
#define NQ   4096
#define E    256
#define NH   8
#define NP   4
#define HD   32
#define HH   64
#define WW   64
#define M_TOT (BS*NQ)      // 32768
#define N1   352

// GEMM tiling
#define BM   128
#define BN   128
#define BK   32
#define LDAH 40                    // bf16 leading dim (80B rows)
#define LDC  136                   // float C staging leading dim
#define NKT  (E/BK)                // 8
#define STAGE ((BM+BN)*LDAH)       // 10240 bf16 per stage
#define DYN_SMEM 69632             // max(2*STAGE*2 = 40960, BM*LDC*4 = 69632)

// Scratch
__device__ __nv_bfloat16 g_qb  [M_TOT*E];             // query bf16
__device__ __nv_bfloat16 g_val [BS*NH*NQ*HD + 4096];  // [b,h,pos,d] + guard pad
__device__ float         g_off [M_TOT*64];
__device__ float         g_attn[M_TOT*32];
__device__ __nv_bfloat16 g_samp[M_TOT*E];
__device__ __nv_bfloat16 g_w1  [N1*E];
__device__ __nv_bfloat16 g_w2  [E*E];
__device__ float         g_b1  [N1];
__device__ float4        g_sw  [M_TOT*NH*NP];         // premult corner weights
__device__ int           g_sidx[M_TOT*NH*NP];         // clamped base index

// ---------------------------------------------------------------------------
__device__ __forceinline__ void cp_async16(void* sdst, const void* gsrc) {
    unsigned s = (unsigned)__cvta_generic_to_shared(sdst);
    asm volatile("cp.async.cg.shared.global [%0], [%1], 16;\n" :: "r"(s), "l"(gsrc));
}

// ---------------------------------------------------------------------------
// Prep (fused): blocks [0,4096) convert query fp32->bf16; blocks [4096,4448)
// convert/concat weights and biases.
// ---------------------------------------------------------------------------
__global__ __launch_bounds__(256) void prep_all(
        const float* __restrict__ qsrc,
        const float* __restrict__ vw, const float* __restrict__ vb,
        const float* __restrict__ ow, const float* __restrict__ ob,
        const float* __restrict__ aw, const float* __restrict__ ab,
        const float* __restrict__ outw) {
    if (blockIdx.x < 4096) {
        int i = (blockIdx.x * 256 + threadIdx.x) * 8;
        float4 u = *(const float4*)&qsrc[i];
        float4 v = *(const float4*)&qsrc[i + 4];
        __nv_bfloat16 t[8] = {
            __float2bfloat16(u.x), __float2bfloat16(u.y),
            __float2bfloat16(u.z), __float2bfloat16(u.w),
            __float2bfloat16(v.x), __float2bfloat16(v.y),
            __float2bfloat16(v.z), __float2bfloat16(v.w)};
        *(uint4*)&g_qb[i] = *(uint4*)t;
    } else {
        int i = (blockIdx.x - 4096) * 256 + threadIdx.x;
        if (i < 256*256)      g_w1[i] = __float2bfloat16(vw[i]);
        else if (i < 320*256) g_w1[i] = __float2bfloat16(ow[i - 256*256]);
        else if (i < 352*256) g_w1[i] = __float2bfloat16(aw[i - 320*256]);
        if (i < 256*256)      g_w2[i] = __float2bfloat16(outw[i]);
        if (i < 256)          g_b1[i] = vb[i];
        else if (i < 320)     g_b1[i] = ob[i - 256];
        else if (i < 352)     g_b1[i] = ab[i - 320];
    }
}

// ---------------------------------------------------------------------------
// bf16 cp.async pipelined mainloop: C[BM][BN] = A @ B^T staged to smem (fp32).
// ---------------------------------------------------------------------------
__device__ __forceinline__ void bf16_mainloop(
    const __nv_bfloat16* __restrict__ A, const __nv_bfloat16* __restrict__ B,
    int b_rows, int m0, int n0, unsigned char* smem_raw)
{
    __nv_bfloat16* buf = (__nv_bfloat16*)smem_raw;
    const int tid  = threadIdx.x;
    const int warp = tid >> 5;
    const int wr   = warp >> 2;    // 0..1 -> 64-row block
    const int wc   = warp & 3;     // 0..3 -> 32-col block

    wmma::fragment<wmma::accumulator, 16, 16, 16, float> c[4][2];
    #pragma unroll
    for (int i = 0; i < 4; i++)
        #pragma unroll
        for (int j = 0; j < 2; j++) wmma::fill_fragment(c[i][j], 0.0f);

    auto issue = [&](int s, int k0) {
        __nv_bfloat16* St = buf + s * STAGE;
        #pragma unroll
        for (int it = 0; it < 4; it++) {
            int idx = tid + it * 256;
            int row = idx >> 2, cg = idx & 3;
            const __nv_bfloat16* src;
            if (row < BM) {
                src = A + (size_t)(m0 + row) * E + k0 + cg * 8;
            } else {
                int gn = n0 + row - BM;
                if (gn >= b_rows) gn = b_rows - 1;
                src = B + (size_t)gn * E + k0 + cg * 8;
            }
            cp_async16(St + row * LDAH + cg * 8, src);
        }
        asm volatile("cp.async.commit_group;\n" ::);
    };

    auto compute = [&](int s) {
        __nv_bfloat16* As = buf + s * STAGE;
        __nv_bfloat16* Bs = As + BM * LDAH;
        #pragma unroll
        for (int kk = 0; kk < BK; kk += 16) {
            wmma::fragment<wmma::matrix_a, 16, 16, 16, __nv_bfloat16, wmma::row_major> a[4];
            wmma::fragment<wmma::matrix_b, 16, 16, 16, __nv_bfloat16, wmma::col_major> b[2];
            #pragma unroll
            for (int i = 0; i < 4; i++)
                wmma::load_matrix_sync(a[i], &As[(wr * 64 + i * 16) * LDAH + kk], LDAH);
            #pragma unroll
            for (int j = 0; j < 2; j++)
                wmma::load_matrix_sync(b[j], &Bs[(wc * 32 + j * 16) * LDAH + kk], LDAH);
            #pragma unroll
            for (int i = 0; i < 4; i++)
                #pragma unroll
                for (int j = 0; j < 2; j++)
                    wmma::mma_sync(c[i][j], a[i], b[j], c[i][j]);
        }
    };

    issue(0, 0);
    for (int kt = 0; kt < NKT; kt++) {
        if (kt + 1 < NKT) {
            issue((kt + 1) & 1, (kt + 1) * BK);
            asm volatile("cp.async.wait_group 1;\n" ::);
        } else {
            asm volatile("cp.async.wait_group 0;\n" ::);
        }
        __syncthreads();
        compute(kt & 1);
        __syncthreads();
    }

    float* Cs = (float*)smem_raw;
    #pragma unroll
    for (int i = 0; i < 4; i++)
        #pragma unroll
        for (int j = 0; j < 2; j++)
            wmma::store_matrix_sync(&Cs[(wr * 64 + i * 16) * LDC + wc * 32 + j * 16],
                                    c[i][j], LDC, wmma::mem_row_major);
    __syncthreads();
}

// ---------------------------------------------------------------------------
// GEMM1: g_qb @ g_w1^T (+bias) -> scatter {g_val bf16, g_off, g_attn}
// ---------------------------------------------------------------------------
__global__ __launch_bounds__(256) void gemm1_tc() {
    extern __shared__ unsigned char smem_raw[];
    const int m0 = blockIdx.x * BM;
    const int n0 = blockIdx.y * BN;
    const int tid = threadIdx.x;

    bf16_mainloop(g_qb, g_w1, N1, m0, n0, smem_raw);
    float* Cs = (float*)smem_raw;

    #pragma unroll
    for (int it = 0; it < 16; it++) {
        int idx = tid + it * 256;
        int mm = idx >> 5, n4 = idx & 31;
        int c = n0 + n4 * 4;
        if (c >= N1) continue;
        int m = m0 + mm;
        int b = m >> 12, q = m & 4095;
        float4 v = *(float4*)&Cs[mm * LDC + n4 * 4];
        v.x += g_b1[c];     v.y += g_b1[c + 1];
        v.z += g_b1[c + 2]; v.w += g_b1[c + 3];
        if (c < 256) {
            int h = c >> 5, d = c & 31;
            __nv_bfloat16 t[4] = {__float2bfloat16(v.x), __float2bfloat16(v.y),
                                  __float2bfloat16(v.z), __float2bfloat16(v.w)};
            *(uint2*)&g_val[((((size_t)b << 3) + h) * NQ + q) * HD + d] = *(uint2*)t;
        } else if (c < 320) {
            *(float4*)&g_off[(size_t)m * 64 + (c - 256)] = v;
        } else {
            *(float4*)&g_attn[(size_t)m * 32 + (c - 320)] = v;
        }
    }
}

// ---------------------------------------------------------------------------
// GEMM2: g_samp @ g_w2^T + out_b + 2*query -> out
// ---------------------------------------------------------------------------
__global__ __launch_bounds__(256) void gemm2_tc(const float* __restrict__ bias,
                                                const float* __restrict__ query,
                                                float* __restrict__ out) {
    extern __shared__ unsigned char smem_raw[];
    const int m0 = blockIdx.x * BM;
    const int n0 = blockIdx.y * BN;
    const int tid = threadIdx.x;

    bf16_mainloop(g_samp, g_w2, E, m0, n0, smem_raw);
    float* Cs = (float*)smem_raw;

    #pragma unroll
    for (int it = 0; it < 16; it++) {
        int idx = tid + it * 256;
        int mm = idx >> 5, n4 = idx & 31;
        int c = n0 + n4 * 4;
        size_t go = (size_t)(m0 + mm) * E + c;
        float4 v = *(float4*)&Cs[mm * LDC + n4 * 4];
        float4 bi = *(const float4*)&bias[c];
        float4 qv = *(const float4*)&query[go];
        v.x += bi.x + 2.0f * qv.x;
        v.y += bi.y + 2.0f * qv.y;
        v.z += bi.z + 2.0f * qv.z;
        v.w += bi.w + 2.0f * qv.w;
        *(float4*)&out[go] = v;
    }
}

// ---------------------------------------------------------------------------
// Sample setup: one thread per (m,h,p). Computes softmax-premultiplied,
// validity-masked corner weights + clamped base index.
// Low-side clamp fix: when ix<0 (resp. iy<0) the valid neighbor sits AT the
// clamped base, so its weight moves into the base slot (other slot zeroed).
// High-side overreads keep zero weight and stay in-bounds via tail padding.
// ---------------------------------------------------------------------------
__global__ __launch_bounds__(256) void sample_setup() {
    const int t  = blockIdx.x * 256 + threadIdx.x;
    const int p  = t & 3;
    const int mh = t >> 2;          // m*8 + h
    const int m  = mh >> 3;
    const int q  = m & 4095;

    const float4 at = *(const float4*)&g_attn[(size_t)mh * 4];
    float mx = fmaxf(fmaxf(at.x, at.y), fmaxf(at.z, at.w));
    float e0 = __expf(at.x - mx), e1 = __expf(at.y - mx),
          e2 = __expf(at.z - mx), e3 = __expf(at.w - mx);
    float inv = 1.f / (e0 + e1 + e2 + e3);
    float awp = (p == 0 ? e0 : p == 1 ? e1 : p == 2 ? e2 : e3) * inv;

    const float2 off = *(const float2*)&g_off[(size_t)mh * 8 + p * 2];
    const float px = (float)(q & 63) * (64.0f / 63.0f) + off.x - 0.5f;
    const float py = (float)(q >> 6) * (64.0f / 63.0f) + off.y - 0.5f;
    const float fx = floorf(px), fy = floorf(py);
    const float wx = px - fx, wy = py - fy;
    const int ix = (int)fx, iy = (int)fy;

    float wxl = (ix >= 0  && ix < 64) ? (1.f - wx) : 0.f;
    float wxr = (ix >= -1 && ix < 63) ? wx         : 0.f;
    if (ix < 0) { wxl = wxr; wxr = 0.f; }   // valid right neighbor lives at base (x=0)
    float wyt = (iy >= 0  && iy < 64) ? (1.f - wy) : 0.f;
    float wyb = (iy >= -1 && iy < 63) ? wy         : 0.f;
    if (iy < 0) { wyt = wyb; wyb = 0.f; }   // valid bottom neighbor lives at base (y=0)
    wyt *= awp;
    wyb *= awp;

    const int ix0 = min(max(ix, 0), 63);
    const int iy0 = min(max(iy, 0), 63);

    g_sw[t]   = make_float4(wxl * wyt, wxr * wyt, wxl * wyb, wxr * wyb);
    g_sidx[t] = (iy0 << 11) + (ix0 << 5);
}

// ---------------------------------------------------------------------------
// Gather: warp = 2 heads of one query; lane = (head, point, channel-group).
// Pure gather+FMA; all setup precomputed. Corner offsets +0,+32,+2048,+2080
// always dereference valid memory (weights zero when logically OOB).
// ---------------------------------------------------------------------------
__global__ __launch_bounds__(256) void sample_gather() {
    const int wid  = blockIdx.x * 8 + (threadIdx.x >> 5);  // 0 .. M_TOT*4-1
    const int lane = threadIdx.x & 31;
    const int m    = wid >> 2;
    const int h    = ((wid & 3) << 1) + (lane >> 4);       // 0..7
    const int p    = (lane >> 2) & 3;
    const int cg   = lane & 3;
    const int mh   = (m << 3) + h;
    const int slab = ((m >> 12) << 3) + h;                 // b*8+h

    const int t = (mh << 2) + p;
    const float4 w = __ldg(&g_sw[t]);
    const int base = __ldg(&g_sidx[t]);

    const __nv_bfloat16* __restrict__ vp =
        g_val + (size_t)slab * (NQ * HD) + base + (cg << 3);

    float acc[8];
    #pragma unroll
    for (int j = 0; j < 8; j++) acc[j] = 0.f;

    #pragma unroll
    for (int cn = 0; cn < 4; cn++) {
        const int  o  = (cn == 0 ? 0 : cn == 1 ? 32 : cn == 2 ? 2048 : 2080);
        const float cw = (cn == 0 ? w.x : cn == 1 ? w.y : cn == 2 ? w.z : w.w);
        uint4 r = *(const uint4*)(vp + o);
        const __nv_bfloat162* h2 = (const __nv_bfloat162*)&r;
        #pragma unroll
        for (int j = 0; j < 4; j++) {
            float2 f = __bfloat1622float2(h2[j]);
            acc[2*j]   = fmaf(cw, f.x, acc[2*j]);
            acc[2*j+1] = fmaf(cw, f.y, acc[2*j+1]);
        }
    }

    // reduce over the 4 points (lane bits 2,3)
    #pragma unroll
    for (int msk = 4; msk <= 8; msk <<= 1)
        #pragma unroll
        for (int j = 0; j < 8; j++)
            acc[j] += __shfl_xor_sync(0xFFFFFFFF, acc[j], msk);

    if (p == 0) {
        __nv_bfloat16 tt[8];
        #pragma unroll
        for (int j = 0; j < 8; j++) tt[j] = __float2bfloat16(acc[j]);
        *(uint4*)&g_samp[(size_t)m * E + h * HD + (cg << 3)] = *(uint4*)tt;
    }
}

// ---------------------------------------------------------------------------
extern "C" void kernel_launch(void* const* d_in, const int* in_sizes, int n_in,
                              void* d_out, int out_size) {
    const float* query   = (const float*)d_in[0];
    const float* value_w = (const float*)d_in[1];
    const float* value_b = (const float*)d_in[2];
    const float* off_w   = (const float*)d_in[3];
    const float* off_b   = (const float*)d_in[4];
    const float* attn_w  = (const float*)d_in[5];
    const float* attn_b  = (const float*)d_in[6];
    const float* out_w   = (const float*)d_in[7];
    const float* out_b   = (const float*)d_in[8];
    float* out = (float*)d_out;

    static bool attr_done = false;
    if (!attr_done) {
        cudaFuncSetAttribute(gemm1_tc, cudaFuncAttributeMaxDynamicSharedMemorySize, DYN_SMEM);
        cudaFuncSetAttribute(gemm2_tc, cudaFuncAttributeMaxDynamicSharedMemorySize, DYN_SMEM);
        attr_done = true;
    }

    prep_all<<<4096 + 352, 256>>>(query, value_w, value_b, off_w, off_b,
                                  attn_w, attn_b, out_w);

    dim3 g1(M_TOT / BM, (N1 + BN - 1) / BN);   // 256 x 3
    gemm1_tc<<<g1, 256, DYN_SMEM>>>();

    sample_setup<<<(M_TOT * NH * NP) / 256, 256>>>();
    sample_gather<<<(M_TOT * 4) / 8, 256>>>();

    dim3 g2(M_TOT / BM, E / BN);               // 256 x 2
    gemm2_tc<<<g2, 256, DYN_SMEM>>>(out_b, query, out);
}